// round 4
// baseline (speedup 1.0000x reference)
#include <cuda_runtime.h>
#include <math.h>

#define NN   20000
#define EE   320000
#define TT   12
#define HH   64
#define CINN 16
#define FF   768      // TT*HH
#define NPB  8        // nodes per block

// ---------------- scratch (static device globals; no runtime allocation) ----
__device__ float g_bufA[(size_t)NN * FF];   // ping
__device__ float g_bufB[(size_t)NN * FF];   // pong
__device__ int   g_cnt[NN];
__device__ int   g_rowptr[NN];
__device__ int   g_fill[NN];
__device__ float g_dinv[NN];
__device__ float g_selfc[NN];
__device__ int   g_col[EE];
__device__ float g_coef[EE];

// ---------------- graph preprocessing --------------------------------------
__global__ void k_zero() {
    int i = blockIdx.x * blockDim.x + threadIdx.x;
    if (i < NN) { g_cnt[i] = 0; g_fill[i] = 0; }
}

__global__ void k_count(const int* __restrict__ dst) {
    int e = blockIdx.x * blockDim.x + threadIdx.x;
    if (e < EE) atomicAdd(&g_cnt[dst[e]], 1);
}

// single-block exclusive scan of g_cnt -> g_rowptr (N=20000 <= 1024*20)
__global__ void k_scan() {
    __shared__ int s[1024];
    int tid = threadIdx.x;
    int base = tid * 20;
    int loc[20];
    int tot = 0;
#pragma unroll
    for (int i = 0; i < 20; i++) {
        int idx = base + i;
        int v = (idx < NN) ? g_cnt[idx] : 0;
        loc[i] = tot; tot += v;
    }
    s[tid] = tot;
    __syncthreads();
    for (int off = 1; off < 1024; off <<= 1) {
        int v = (tid >= off) ? s[tid - off] : 0;
        __syncthreads();
        s[tid] += v;
        __syncthreads();
    }
    int exc = s[tid] - tot;
#pragma unroll
    for (int i = 0; i < 20; i++) {
        int idx = base + i;
        if (idx < NN) g_rowptr[idx] = exc + loc[i];
    }
}

__global__ void k_dinv() {
    int i = blockIdx.x * blockDim.x + threadIdx.x;
    if (i < NN) {
        float d = (float)(g_cnt[i] + 1);   // +1 self loop
        g_dinv[i]  = rsqrtf(d);
        g_selfc[i] = 1.0f / d;
    }
}

__global__ void k_fill(const int* __restrict__ src, const int* __restrict__ dst) {
    int e = blockIdx.x * blockDim.x + threadIdx.x;
    if (e < EE) {
        int s = src[e], d = dst[e];
        int p = g_rowptr[d] + atomicAdd(&g_fill[d], 1);
        g_col[p]  = s;
        g_coef[p] = g_dinv[s] * g_dinv[d];
    }
}

// ---------------- embedding: out flat[t*64+h] = relu(x[n,t,:]@We + be) -----
__global__ __launch_bounds__(256) void k_embed(
    const float* __restrict__ x, const float* __restrict__ We,
    const float* __restrict__ be, float* __restrict__ out)
{
    __shared__ float sWe[CINN * HH];
    __shared__ float sbe[HH];
    __shared__ float sx[NPB][TT * CINN];
    int tid = threadIdx.x, lane = tid & 31, w = tid >> 5;
    for (int i = tid; i < CINN * HH; i += 256) sWe[i] = We[i];
    if (tid < HH) sbe[tid] = be[tid];
    int node = blockIdx.x * NPB + w;
    const float* xr = x + (size_t)node * (TT * CINN);
#pragma unroll
    for (int j = 0; j < 6; j++) sx[w][lane + 32 * j] = xr[lane + 32 * j];
    __syncthreads();
    float* orow = out + (size_t)node * FF;
#pragma unroll
    for (int t = 0; t < TT; t++) {
        float a0 = sbe[lane], a1 = sbe[lane + 32];
#pragma unroll
        for (int c = 0; c < CINN; c++) {
            float xv = sx[w][t * CINN + c];
            a0 += xv * sWe[c * HH + lane];
            a1 += xv * sWe[c * HH + lane + 32];
        }
        orow[t * HH + lane]      = fmaxf(a0, 0.f);
        orow[t * HH + lane + 32] = fmaxf(a1, 0.f);
    }
}

// ---------------- fused ST layer -------------------------------------------
// flat view inside layers: element (c,t) lives at flat[c*12+t]
// phase1: agg = selfc*xi[n] + sum_edges coef*xi[src]      (warp per node)
// phase2: g[d,t] = gcn_b[d] + sum_c agg[c,t]*W[c,d]
// phase3: conv(k=3,pad=1) over t + BN + residual(xi) + relu
#define LAYER_SMEM ((4096 + 12288 + 2 * NPB * FF) * 4)   // 114688 B

__global__ __launch_bounds__(256, 2) void k_layer(
    const float* __restrict__ xin, float* __restrict__ xout,
    const float* __restrict__ W,   const float* __restrict__ b,
    const float* __restrict__ cw,  const float* __restrict__ cb,
    const float* __restrict__ bng, const float* __restrict__ bnb,
    const float* __restrict__ bnm, const float* __restrict__ bnv)
{
    extern __shared__ float sm[];
    float* sW   = sm;                        // [c*64+d]        16 KB
    float* sCW  = sm + 4096;                 // [(i*3+k)*64+o]  48 KB
    float* sAgg = sm + 4096 + 12288;         // [NPB][768]      24 KB
    float* sG   = sAgg + NPB * FF;           // [NPB][768]      24 KB

    int tid = threadIdx.x, lane = tid & 31, w = tid >> 5;
    int node = blockIdx.x * NPB + w;

    for (int i = tid; i < 4096; i += 256) sW[i] = W[i];
    for (int i = tid; i < 12288; i += 256) {
        int o = i & 63, ik = i >> 6;         // ik = i*3+k
        sCW[i] = cw[o * 192 + ik];
    }

    // ---- phase 1: CSR gather-aggregate (per-warp, 24 regs/lane) ----
    const float* xrow = xin + (size_t)node * FF;
    float acc[24];
    float sc = g_selfc[node];
#pragma unroll
    for (int j = 0; j < 24; j++) acc[j] = sc * xrow[lane + 32 * j];
    int rp = g_rowptr[node], ne = g_cnt[node];
    for (int e = 0; e < ne; e++) {
        int   srcn = __ldg(&g_col[rp + e]);
        float cf   = __ldg(&g_coef[rp + e]);
        const float* srow = xin + (size_t)srcn * FF;
#pragma unroll
        for (int j = 0; j < 24; j++) acc[j] += cf * __ldg(&srow[lane + 32 * j]);
    }
    float* sA = sAgg + w * FF;
#pragma unroll
    for (int j = 0; j < 24; j++) sA[lane + 32 * j] = acc[j];
    __syncthreads();

    // ---- phase 2: GCN matmul (thread: d in {lane, lane+32}, all 12 t) ----
    float* sGr = sG + w * FF;
    {
        int d0 = lane, d1 = lane + 32;
        float a0[12], a1[12];
        float b0v = b[d0], b1v = b[d1];
#pragma unroll
        for (int t = 0; t < 12; t++) { a0[t] = b0v; a1[t] = b1v; }
#pragma unroll 4
        for (int c = 0; c < 64; c++) {
            float w0 = sW[c * 64 + d0], w1 = sW[c * 64 + d1];
#pragma unroll
            for (int t = 0; t < 12; t++) {
                float av = sA[c * 12 + t];       // LDS broadcast
                a0[t] += av * w0;
                a1[t] += av * w1;
            }
        }
#pragma unroll
        for (int t = 0; t < 12; t++) { sGr[d0 * 12 + t] = a0[t]; sGr[d1 * 12 + t] = a1[t]; }
    }
    __syncthreads();

    // ---- phase 3: temporal conv + BN + residual + relu ----
    {
        int o0 = lane, o1 = lane + 32;
        float c0[12], c1[12];
        float cb0 = cb[o0], cb1 = cb[o1];
#pragma unroll
        for (int t = 0; t < 12; t++) { c0[t] = cb0; c1[t] = cb1; }
#pragma unroll 2
        for (int i = 0; i < 64; i++) {
            float gv[12];
#pragma unroll
            for (int t = 0; t < 12; t++) gv[t] = sGr[i * 12 + t];
            const float* wp = sCW + i * 192;
            float w00 = wp[o0], w01 = wp[64 + o0], w02 = wp[128 + o0];
            float w10 = wp[o1], w11 = wp[64 + o1], w12 = wp[128 + o1];
#pragma unroll
            for (int t = 0; t < 12; t++) {
                float lft = (t > 0)  ? gv[t - 1] : 0.f;
                float mid = gv[t];
                float rgt = (t < 11) ? gv[t + 1] : 0.f;
                c0[t] += lft * w00 + mid * w01 + rgt * w02;
                c1[t] += lft * w10 + mid * w11 + rgt * w12;
            }
        }
        float s0 = bng[o0] * rsqrtf(bnv[o0] + 1e-5f);
        float s1 = bng[o1] * rsqrtf(bnv[o1] + 1e-5f);
        float h0 = bnb[o0] - bnm[o0] * s0;
        float h1 = bnb[o1] - bnm[o1] * s1;
        float* orow = xout + (size_t)node * FF;
#pragma unroll
        for (int t = 0; t < 12; t++) {
            float v0 = c0[t] * s0 + h0 + xrow[o0 * 12 + t];
            float v1 = c1[t] * s1 + h1 + xrow[o1 * 12 + t];
            orow[o0 * 12 + t] = fmaxf(v0, 0.f);
            orow[o1 * 12 + t] = fmaxf(v1, 0.f);
        }
    }
}

// ---------------- dual attention pooling + output MLP ----------------------
__global__ __launch_bounds__(256) void k_attn(
    const float* __restrict__ xin, float* __restrict__ out,
    const float* __restrict__ taw1, const float* __restrict__ tab1,
    const float* __restrict__ taw2, const float* __restrict__ tab2,
    const float* __restrict__ faw1, const float* __restrict__ fab1,
    const float* __restrict__ faw2, const float* __restrict__ fab2,
    const float* __restrict__ ow1,  const float* __restrict__ ob1,
    const float* __restrict__ ow2,  const float* __restrict__ ob2)
{
    __shared__ float sXa[NPB][FF];           // 24 KB
    __shared__ float sTW1[HH * 32];          // 8 KB
    __shared__ float sOW1[HH * 32];          // 8 KB
    __shared__ float sTB1[32], sTW2[32], sOB1[32], sOW2[32];
    __shared__ float sFW1[TT * 6], sFB1[6], sFW2[6];

    int tid = threadIdx.x, lane = tid & 31, w = tid >> 5;
    for (int i = tid; i < HH * 32; i += 256) { sTW1[i] = taw1[i]; sOW1[i] = ow1[i]; }
    if (tid < 32) { sTB1[tid] = tab1[tid]; sTW2[tid] = taw2[tid];
                    sOB1[tid] = ob1[tid];  sOW2[tid] = ow2[tid]; }
    if (tid < TT * 6) sFW1[tid] = faw1[tid];
    if (tid < 6) { sFB1[tid] = fab1[tid]; sFW2[tid] = faw2[tid]; }

    int node = blockIdx.x * NPB + w;
    const float* xr = xin + (size_t)node * FF;
#pragma unroll
    for (int j = 0; j < 24; j++) sXa[w][lane + 32 * j] = xr[lane + 32 * j];
    __syncthreads();

    float tab2v = tab2[0], fab2v = fab2[0], ob2v = ob2[0];

    // temporal attention scores (lane j computes hidden unit j)
    float tw[12];
#pragma unroll
    for (int t = 0; t < 12; t++) {
        float m = sTB1[lane];
#pragma unroll
        for (int h = 0; h < 64; h++) m += sXa[w][t * 64 + h] * sTW1[h * 32 + lane];
        m = fmaxf(m, 0.f);
        float c = m * sTW2[lane];
#pragma unroll
        for (int off = 16; off; off >>= 1) c += __shfl_xor_sync(0xffffffffu, c, off);
        tw[t] = c + tab2v;
    }
    // softmax over T (replicated per lane)
    float mx = tw[0];
#pragma unroll
    for (int t = 1; t < 12; t++) mx = fmaxf(mx, tw[t]);
    float ssum = 0.f;
#pragma unroll
    for (int t = 0; t < 12; t++) { tw[t] = expf(tw[t] - mx); ssum += tw[t]; }
    float inv = 1.f / ssum;
#pragma unroll
    for (int t = 0; t < 12; t++) tw[t] *= inv;

    // feature attention: lane owns h0=lane, h1=lane+32
    float xt0[12], xt1[12];
#pragma unroll
    for (int t = 0; t < 12; t++) {
        xt0[t] = sXa[w][t * 64 + lane]      * tw[t];
        xt1[t] = sXa[w][t * 64 + lane + 32] * tw[t];
    }
    float fs0 = fab2v, fs1 = fab2v;
#pragma unroll
    for (int j = 0; j < 6; j++) {
        float v0 = sFB1[j], v1 = sFB1[j];
#pragma unroll
        for (int t = 0; t < 12; t++) {
            float wv = sFW1[t * 6 + j];
            v0 += xt0[t] * wv;
            v1 += xt1[t] * wv;
        }
        v0 = fmaxf(v0, 0.f); v1 = fmaxf(v1, 0.f);
        float w2 = sFW2[j];
        fs0 += v0 * w2; fs1 += v1 * w2;
    }
    // softmax over H (64 values spread over 32 lanes x 2)
    float m2 = fmaxf(fs0, fs1);
#pragma unroll
    for (int off = 16; off; off >>= 1) m2 = fmaxf(m2, __shfl_xor_sync(0xffffffffu, m2, off));
    float e0 = expf(fs0 - m2), e1 = expf(fs1 - m2);
    float es = e0 + e1;
#pragma unroll
    for (int off = 16; off; off >>= 1) es += __shfl_xor_sync(0xffffffffu, es, off);
    float fw0 = e0 / es, fw1 = e1 / es;

    float sum0 = 0.f, sum1 = 0.f;
#pragma unroll
    for (int t = 0; t < 12; t++) { sum0 += xt0[t]; sum1 += xt1[t]; }
    float xf0 = fw0 * sum0, xf1 = fw1 * sum1;

    __syncwarp();
    sXa[w][lane] = xf0; sXa[w][lane + 32] = xf1;
    __syncwarp();

    // output MLP
    float y = sOB1[lane];
#pragma unroll
    for (int h = 0; h < 64; h++) y += sXa[w][h] * sOW1[h * 32 + lane];
    y = fmaxf(y, 0.f);
    float c2 = y * sOW2[lane];
#pragma unroll
    for (int off = 16; off; off >>= 1) c2 += __shfl_xor_sync(0xffffffffu, c2, off);
    if (lane == 0) out[node] = c2 + ob2v;
}

// ---------------- launch ----------------------------------------------------
extern "C" void kernel_launch(void* const* d_in, const int* in_sizes, int n_in,
                              void* d_out, int out_size)
{
    const float* x    = (const float*)d_in[0];
    const int*   ei   = (const int*)d_in[1];
    const int*   srcp = ei;
    const int*   dstp = ei + EE;
    const float* We   = (const float*)d_in[2];
    const float* be   = (const float*)d_in[3];
    const float* gW   = (const float*)d_in[4];
    const float* gb   = (const float*)d_in[5];
    const float* cw   = (const float*)d_in[6];
    const float* cb   = (const float*)d_in[7];
    const float* bng  = (const float*)d_in[8];
    const float* bnb  = (const float*)d_in[9];
    const float* bnm  = (const float*)d_in[10];
    const float* bnv  = (const float*)d_in[11];
    const float* taw1 = (const float*)d_in[12];
    const float* tab1 = (const float*)d_in[13];
    const float* taw2 = (const float*)d_in[14];
    const float* tab2 = (const float*)d_in[15];
    const float* faw1 = (const float*)d_in[16];
    const float* fab1 = (const float*)d_in[17];
    const float* faw2 = (const float*)d_in[18];
    const float* fab2 = (const float*)d_in[19];
    const float* ow1  = (const float*)d_in[20];
    const float* ob1  = (const float*)d_in[21];
    const float* ow2  = (const float*)d_in[22];
    const float* ob2  = (const float*)d_in[23];
    float* out = (float*)d_out;

    cudaFuncSetAttribute(k_layer, cudaFuncAttributeMaxDynamicSharedMemorySize, LAYER_SMEM);

    void *pA = nullptr, *pB = nullptr;
    cudaGetSymbolAddress(&pA, g_bufA);
    cudaGetSymbolAddress(&pB, g_bufB);
    float* bufA = (float*)pA;
    float* bufB = (float*)pB;

    // --- graph preprocessing ---
    k_zero <<<(NN + 255) / 256, 256>>>();
    k_count<<<(EE + 255) / 256, 256>>>(dstp);
    k_scan <<<1, 1024>>>();
    k_dinv <<<(NN + 255) / 256, 256>>>();
    k_fill <<<(EE + 255) / 256, 256>>>(srcp, dstp);

    // --- embedding ---
    k_embed<<<NN / NPB, 256>>>(x, We, be, bufA);

    // --- 3 fused ST layers (ping-pong) ---
    k_layer<<<NN / NPB, 256, LAYER_SMEM>>>(bufA, bufB,
        gW + 0 * HH * HH, gb + 0 * HH, cw + 0 * HH * HH * 3, cb + 0 * HH,
        bng + 0 * HH, bnb + 0 * HH, bnm + 0 * HH, bnv + 0 * HH);
    k_layer<<<NN / NPB, 256, LAYER_SMEM>>>(bufB, bufA,
        gW + 1 * HH * HH, gb + 1 * HH, cw + 1 * HH * HH * 3, cb + 1 * HH,
        bng + 1 * HH, bnb + 1 * HH, bnm + 1 * HH, bnv + 1 * HH);
    k_layer<<<NN / NPB, 256, LAYER_SMEM>>>(bufA, bufB,
        gW + 2 * HH * HH, gb + 2 * HH, cw + 2 * HH * HH * 3, cb + 2 * HH,
        bng + 2 * HH, bnb + 2 * HH, bnm + 2 * HH, bnv + 2 * HH);

    // --- attention pooling + output MLP ---
    k_attn<<<NN / NPB, 256>>>(bufB, out,
        taw1, tab1, taw2, tab2, faw1, fab1, faw2, fab2,
        ow1, ob1, ow2, ob2);
}

// round 5
// speedup vs baseline: 1.2182x; 1.2182x over previous
#include <cuda_runtime.h>
#include <math.h>

#define NN   20000
#define EE   320000
#define TT   12
#define HH   64
#define CINN 16
#define FF   768      // TT*HH
#define NPB  8        // nodes per block

// ---------------- scratch (static device globals) ---------------------------
__device__ float g_bufA[(size_t)NN * FF];
__device__ float g_bufB[(size_t)NN * FF];
__device__ int   g_cnt[NN];
__device__ int   g_rowptr[NN];
__device__ int   g_fill[NN];
__device__ float g_dinv[NN];
__device__ float g_selfc[NN];
__device__ int   g_col[EE];
__device__ float g_coef[EE];

// ---------------- f32x2 helpers ---------------------------------------------
__device__ __forceinline__ unsigned long long pk2(float lo, float hi) {
    unsigned long long r;
    asm("mov.b64 %0,{%1,%2};" : "=l"(r) : "f"(lo), "f"(hi));
    return r;
}
__device__ __forceinline__ void upk2(unsigned long long p, float& lo, float& hi) {
    asm("mov.b64 {%0,%1}, %2;" : "=f"(lo), "=f"(hi) : "l"(p));
}
__device__ __forceinline__ unsigned long long fma2(
    unsigned long long a, unsigned long long b, unsigned long long c) {
    unsigned long long d;
    asm("fma.rn.f32x2 %0,%1,%2,%3;" : "=l"(d) : "l"(a), "l"(b), "l"(c));
    return d;
}

// ---------------- graph preprocessing ----------------------------------------
__global__ void k_zero() {
    int i = blockIdx.x * blockDim.x + threadIdx.x;
    if (i < NN) g_cnt[i] = 0;
}

__global__ void k_count(const int* __restrict__ dst) {
    int e = blockIdx.x * blockDim.x + threadIdx.x;
    if (e < EE) atomicAdd(&g_cnt[dst[e]], 1);
}

// single-block: exclusive scan of g_cnt -> g_rowptr, plus dinv/selfc/fill=0
__global__ void k_scan() {
    __shared__ int s[1024];
    int tid = threadIdx.x;
    int base = tid * 20;
    int loc[20], cv[20];
    int tot = 0;
#pragma unroll
    for (int i = 0; i < 20; i++) {
        int idx = base + i;
        int v = (idx < NN) ? g_cnt[idx] : 0;
        cv[i] = v; loc[i] = tot; tot += v;
    }
    s[tid] = tot;
    __syncthreads();
    for (int off = 1; off < 1024; off <<= 1) {
        int v = (tid >= off) ? s[tid - off] : 0;
        __syncthreads();
        s[tid] += v;
        __syncthreads();
    }
    int exc = s[tid] - tot;
#pragma unroll
    for (int i = 0; i < 20; i++) {
        int idx = base + i;
        if (idx < NN) {
            g_rowptr[idx] = exc + loc[i];
            g_fill[idx] = 0;
            float d = (float)(cv[i] + 1);
            g_dinv[idx]  = rsqrtf(d);
            g_selfc[idx] = 1.0f / d;
        }
    }
}

__global__ void k_fill(const int* __restrict__ src, const int* __restrict__ dst) {
    int e = blockIdx.x * blockDim.x + threadIdx.x;
    if (e < EE) {
        int s = src[e], d = dst[e];
        int p = g_rowptr[d] + atomicAdd(&g_fill[d], 1);
        g_col[p]  = s;
        g_coef[p] = g_dinv[s] * g_dinv[d];
    }
}

// ---------------- embedding --------------------------------------------------
__global__ __launch_bounds__(256) void k_embed(
    const float* __restrict__ x, const float* __restrict__ We,
    const float* __restrict__ be, float* __restrict__ out)
{
    __shared__ float sWe[CINN * HH];
    __shared__ float sbe[HH];
    __shared__ float sx[NPB][TT * CINN];
    int tid = threadIdx.x, lane = tid & 31, w = tid >> 5;
    for (int i = tid; i < CINN * HH; i += 256) sWe[i] = We[i];
    if (tid < HH) sbe[tid] = be[tid];
    int node = blockIdx.x * NPB + w;
    const float* xr = x + (size_t)node * (TT * CINN);
#pragma unroll
    for (int j = 0; j < 6; j++) sx[w][lane + 32 * j] = xr[lane + 32 * j];
    __syncthreads();
    float* orow = out + (size_t)node * FF;
#pragma unroll
    for (int t = 0; t < TT; t++) {
        float a0 = sbe[lane], a1 = sbe[lane + 32];
#pragma unroll
        for (int c = 0; c < CINN; c++) {
            float xv = sx[w][t * CINN + c];
            a0 += xv * sWe[c * HH + lane];
            a1 += xv * sWe[c * HH + lane + 32];
        }
        orow[t * HH + lane]      = fmaxf(a0, 0.f);
        orow[t * HH + lane + 32] = fmaxf(a1, 0.f);
    }
}

// ---------------- fused ST layer ---------------------------------------------
// flat view inside layers: element (c,t) at flat[c*12+t]
// phase1: agg = selfc*xi[n] + sum_e coef*xi[src]     (warp/node, float4 lanes)
// phase2: g[d,t] = gcn_b[d] + sum_c agg[c,t]*W[c,d]  (f32x2 packed over t)
// phase3: conv(3)+BN+residual+relu                   (f32x2 packed over (o,o+32))
#define LAYER_SMEM ((4096 + 12288 + 2 * NPB * FF) * 4)   // 114688 B

__global__ __launch_bounds__(256, 2) void k_layer(
    const float* __restrict__ xin, float* __restrict__ xout,
    const float* __restrict__ W,   const float* __restrict__ b,
    const float* __restrict__ cw,  const float* __restrict__ cb,
    const float* __restrict__ bng, const float* __restrict__ bnb,
    const float* __restrict__ bnm, const float* __restrict__ bnv)
{
    extern __shared__ float sm[];
    float* sW   = sm;                          // [c*64+d]             16 KB
    float* sCW  = sm + 4096;                   // float2 pairs         48 KB
    float* sAgg = sm + 4096 + 12288;           // [NPB][768]           24 KB
    float* sG   = sAgg + NPB * FF;             // [NPB][768]           24 KB
    unsigned long long* sCW2 = (unsigned long long*)sCW;  // [(i*3+k)*32+lane]

    int tid = threadIdx.x, lane = tid & 31, w = tid >> 5;
    int node = blockIdx.x * NPB + w;

    for (int i = tid; i < 4096; i += 256) sW[i] = W[i];
    // conv weights as (o, o+32) pairs: sCW2[(i*3+k)*32 + ln] = (cw[ln][ik], cw[ln+32][ik])
    for (int idx = tid; idx < 6144; idx += 256) {
        int ln = idx & 31, ik = idx >> 5;      // ik = i*3+k
        sCW2[idx] = pk2(cw[ln * 192 + ik], cw[(ln + 32) * 192 + ik]);
    }

    // ---- phase 1: CSR gather-aggregate, float4 lanes, 2x edge unroll ----
    const float4* xrow4 = (const float4*)(xin + (size_t)node * FF);
    const float4* xall4 = (const float4*)xin;
    float4 acc[6];
    float sc = g_selfc[node];
#pragma unroll
    for (int j = 0; j < 6; j++) {
        float4 v = xrow4[j * 32 + lane];
        acc[j] = make_float4(sc * v.x, sc * v.y, sc * v.z, sc * v.w);
    }
    int rp = g_rowptr[node], ne = g_cnt[node];
    int e = 0;
    for (; e + 1 < ne; e += 2) {
        int   s0 = __ldg(&g_col[rp + e]),      s1 = __ldg(&g_col[rp + e + 1]);
        float c0 = __ldg(&g_coef[rp + e]),     c1 = __ldg(&g_coef[rp + e + 1]);
        const float4* r0 = xall4 + (size_t)s0 * 192;
        const float4* r1 = xall4 + (size_t)s1 * 192;
        float4 v0[6], v1[6];
#pragma unroll
        for (int j = 0; j < 6; j++) { v0[j] = r0[j * 32 + lane]; v1[j] = r1[j * 32 + lane]; }
#pragma unroll
        for (int j = 0; j < 6; j++) {
            acc[j].x += c0 * v0[j].x + c1 * v1[j].x;
            acc[j].y += c0 * v0[j].y + c1 * v1[j].y;
            acc[j].z += c0 * v0[j].z + c1 * v1[j].z;
            acc[j].w += c0 * v0[j].w + c1 * v1[j].w;
        }
    }
    if (e < ne) {
        int   s0 = __ldg(&g_col[rp + e]);
        float c0 = __ldg(&g_coef[rp + e]);
        const float4* r0 = xall4 + (size_t)s0 * 192;
#pragma unroll
        for (int j = 0; j < 6; j++) {
            float4 v = r0[j * 32 + lane];
            acc[j].x += c0 * v.x; acc[j].y += c0 * v.y;
            acc[j].z += c0 * v.z; acc[j].w += c0 * v.w;
        }
    }
    float* sA = sAgg + w * FF;
#pragma unroll
    for (int j = 0; j < 6; j++) ((float4*)sA)[j * 32 + lane] = acc[j];
    __syncthreads();

    // ---- phase 2: GCN matmul, f32x2 over t-pairs ----
    float* sGr = sG + w * FF;
    int d0 = lane, d1 = lane + 32;
    {
        const unsigned long long* sA2 = (const unsigned long long*)sA;
        unsigned long long a0p[6], a1p[6];
        unsigned long long b0p = pk2(b[d0], b[d0]);
        unsigned long long b1p = pk2(b[d1], b[d1]);
#pragma unroll
        for (int j = 0; j < 6; j++) { a0p[j] = b0p; a1p[j] = b1p; }
#pragma unroll 4
        for (int c = 0; c < 64; c++) {
            float w0 = sW[c * 64 + d0], w1 = sW[c * 64 + d1];
            unsigned long long w0p = pk2(w0, w0), w1p = pk2(w1, w1);
#pragma unroll
            for (int j = 0; j < 6; j++) {
                unsigned long long av = sA2[c * 6 + j];   // LDS.64 broadcast
                a0p[j] = fma2(av, w0p, a0p[j]);
                a1p[j] = fma2(av, w1p, a1p[j]);
            }
        }
        unsigned long long* g0 = (unsigned long long*)(sGr + d0 * 12);
        unsigned long long* g1 = (unsigned long long*)(sGr + d1 * 12);
#pragma unroll
        for (int j = 0; j < 6; j++) { g0[j] = a0p[j]; g1[j] = a1p[j]; }
    }
    __syncthreads();

    // ---- phase 3: temporal conv + BN + residual + relu, f32x2 over (o0,o1) ----
    {
        unsigned long long cp[12];
        unsigned long long cbp = pk2(cb[d0], cb[d1]);
#pragma unroll
        for (int t = 0; t < 12; t++) cp[t] = cbp;
#pragma unroll 2
        for (int i = 0; i < 64; i++) {
            const float2* g2 = (const float2*)(sGr + i * 12);
            float gv[12];
#pragma unroll
            for (int j = 0; j < 6; j++) { float2 g = g2[j]; gv[2 * j] = g.x; gv[2 * j + 1] = g.y; }
            unsigned long long gd[12];
#pragma unroll
            for (int t = 0; t < 12; t++) gd[t] = pk2(gv[t], gv[t]);
            const unsigned long long* wp = sCW2 + i * 96;  // + k*32 + lane
            unsigned long long w0 = wp[lane], w1 = wp[32 + lane], w2 = wp[64 + lane];
#pragma unroll
            for (int t = 0; t < 12; t++) {
                if (t > 0)  cp[t] = fma2(gd[t - 1], w0, cp[t]);
                cp[t] = fma2(gd[t], w1, cp[t]);
                if (t < 11) cp[t] = fma2(gd[t + 1], w2, cp[t]);
            }
        }
        float s0 = bng[d0] * rsqrtf(bnv[d0] + 1e-5f);
        float s1 = bng[d1] * rsqrtf(bnv[d1] + 1e-5f);
        float h0 = bnb[d0] - bnm[d0] * s0;
        float h1 = bnb[d1] - bnm[d1] * s1;
        // residual (vectorized reload of xin row) + store
        float4* orow4 = (float4*)(xout + (size_t)node * FF);
#pragma unroll
        for (int q = 0; q < 3; q++) {
            float4 r0 = xrow4[d0 * 3 + q];
            float4 r1 = xrow4[d1 * 3 + q];
            float c0a, c1a, c0b, c1b, c0c, c1c, c0d, c1d;
            upk2(cp[q * 4 + 0], c0a, c1a);
            upk2(cp[q * 4 + 1], c0b, c1b);
            upk2(cp[q * 4 + 2], c0c, c1c);
            upk2(cp[q * 4 + 3], c0d, c1d);
            float4 o0v = make_float4(
                fmaxf(c0a * s0 + h0 + r0.x, 0.f), fmaxf(c0b * s0 + h0 + r0.y, 0.f),
                fmaxf(c0c * s0 + h0 + r0.z, 0.f), fmaxf(c0d * s0 + h0 + r0.w, 0.f));
            float4 o1v = make_float4(
                fmaxf(c1a * s1 + h1 + r1.x, 0.f), fmaxf(c1b * s1 + h1 + r1.y, 0.f),
                fmaxf(c1c * s1 + h1 + r1.z, 0.f), fmaxf(c1d * s1 + h1 + r1.w, 0.f));
            orow4[d0 * 3 + q] = o0v;
            orow4[d1 * 3 + q] = o1v;
        }
    }
}

// ---------------- dual attention pooling + output MLP ------------------------
__global__ __launch_bounds__(256) void k_attn(
    const float* __restrict__ xin, float* __restrict__ out,
    const float* __restrict__ taw1, const float* __restrict__ tab1,
    const float* __restrict__ taw2, const float* __restrict__ tab2,
    const float* __restrict__ faw1, const float* __restrict__ fab1,
    const float* __restrict__ faw2, const float* __restrict__ fab2,
    const float* __restrict__ ow1,  const float* __restrict__ ob1,
    const float* __restrict__ ow2,  const float* __restrict__ ob2)
{
    __shared__ float sXa[NPB][FF];
    __shared__ float sTW1[HH * 32];
    __shared__ float sOW1[HH * 32];
    __shared__ float sTB1[32], sTW2[32], sOB1[32], sOW2[32];
    __shared__ float sFW1[TT * 6], sFB1[6], sFW2[6];

    int tid = threadIdx.x, lane = tid & 31, w = tid >> 5;
    for (int i = tid; i < HH * 32; i += 256) { sTW1[i] = taw1[i]; sOW1[i] = ow1[i]; }
    if (tid < 32) { sTB1[tid] = tab1[tid]; sTW2[tid] = taw2[tid];
                    sOB1[tid] = ob1[tid];  sOW2[tid] = ow2[tid]; }
    if (tid < TT * 6) sFW1[tid] = faw1[tid];
    if (tid < 6) { sFB1[tid] = fab1[tid]; sFW2[tid] = faw2[tid]; }

    int node = blockIdx.x * NPB + w;
    const float4* xr4 = (const float4*)(xin + (size_t)node * FF);
#pragma unroll
    for (int j = 0; j < 6; j++) ((float4*)sXa[w])[j * 32 + lane] = xr4[j * 32 + lane];
    __syncthreads();

    float tab2v = tab2[0], fab2v = fab2[0], ob2v = ob2[0];

    float tw[12];
#pragma unroll
    for (int t = 0; t < 12; t++) {
        float m = sTB1[lane];
#pragma unroll
        for (int h = 0; h < 64; h++) m += sXa[w][t * 64 + h] * sTW1[h * 32 + lane];
        m = fmaxf(m, 0.f);
        float c = m * sTW2[lane];
#pragma unroll
        for (int off = 16; off; off >>= 1) c += __shfl_xor_sync(0xffffffffu, c, off);
        tw[t] = c + tab2v;
    }
    float mx = tw[0];
#pragma unroll
    for (int t = 1; t < 12; t++) mx = fmaxf(mx, tw[t]);
    float ssum = 0.f;
#pragma unroll
    for (int t = 0; t < 12; t++) { tw[t] = expf(tw[t] - mx); ssum += tw[t]; }
    float inv = 1.f / ssum;
#pragma unroll
    for (int t = 0; t < 12; t++) tw[t] *= inv;

    float xt0[12], xt1[12];
#pragma unroll
    for (int t = 0; t < 12; t++) {
        xt0[t] = sXa[w][t * 64 + lane]      * tw[t];
        xt1[t] = sXa[w][t * 64 + lane + 32] * tw[t];
    }
    float fs0 = fab2v, fs1 = fab2v;
#pragma unroll
    for (int j = 0; j < 6; j++) {
        float v0 = sFB1[j], v1 = sFB1[j];
#pragma unroll
        for (int t = 0; t < 12; t++) {
            float wv = sFW1[t * 6 + j];
            v0 += xt0[t] * wv;
            v1 += xt1[t] * wv;
        }
        v0 = fmaxf(v0, 0.f); v1 = fmaxf(v1, 0.f);
        float w2 = sFW2[j];
        fs0 += v0 * w2; fs1 += v1 * w2;
    }
    float m2 = fmaxf(fs0, fs1);
#pragma unroll
    for (int off = 16; off; off >>= 1) m2 = fmaxf(m2, __shfl_xor_sync(0xffffffffu, m2, off));
    float e0 = expf(fs0 - m2), e1 = expf(fs1 - m2);
    float es = e0 + e1;
#pragma unroll
    for (int off = 16; off; off >>= 1) es += __shfl_xor_sync(0xffffffffu, es, off);
    float fw0 = e0 / es, fw1 = e1 / es;

    float sum0 = 0.f, sum1 = 0.f;
#pragma unroll
    for (int t = 0; t < 12; t++) { sum0 += xt0[t]; sum1 += xt1[t]; }
    float xf0 = fw0 * sum0, xf1 = fw1 * sum1;

    __syncwarp();
    sXa[w][lane] = xf0; sXa[w][lane + 32] = xf1;
    __syncwarp();

    float y = sOB1[lane];
#pragma unroll
    for (int h = 0; h < 64; h++) y += sXa[w][h] * sOW1[h * 32 + lane];
    y = fmaxf(y, 0.f);
    float c2 = y * sOW2[lane];
#pragma unroll
    for (int off = 16; off; off >>= 1) c2 += __shfl_xor_sync(0xffffffffu, c2, off);
    if (lane == 0) out[node] = c2 + ob2v;
}

// ---------------- launch ------------------------------------------------------
extern "C" void kernel_launch(void* const* d_in, const int* in_sizes, int n_in,
                              void* d_out, int out_size)
{
    const float* x    = (const float*)d_in[0];
    const int*   ei   = (const int*)d_in[1];
    const int*   srcp = ei;
    const int*   dstp = ei + EE;
    const float* We   = (const float*)d_in[2];
    const float* be   = (const float*)d_in[3];
    const float* gW   = (const float*)d_in[4];
    const float* gb   = (const float*)d_in[5];
    const float* cw   = (const float*)d_in[6];
    const float* cb   = (const float*)d_in[7];
    const float* bng  = (const float*)d_in[8];
    const float* bnb  = (const float*)d_in[9];
    const float* bnm  = (const float*)d_in[10];
    const float* bnv  = (const float*)d_in[11];
    const float* taw1 = (const float*)d_in[12];
    const float* tab1 = (const float*)d_in[13];
    const float* taw2 = (const float*)d_in[14];
    const float* tab2 = (const float*)d_in[15];
    const float* faw1 = (const float*)d_in[16];
    const float* fab1 = (const float*)d_in[17];
    const float* faw2 = (const float*)d_in[18];
    const float* fab2 = (const float*)d_in[19];
    const float* ow1  = (const float*)d_in[20];
    const float* ob1  = (const float*)d_in[21];
    const float* ow2  = (const float*)d_in[22];
    const float* ob2  = (const float*)d_in[23];
    float* out = (float*)d_out;

    cudaFuncSetAttribute(k_layer, cudaFuncAttributeMaxDynamicSharedMemorySize, LAYER_SMEM);

    void *pA = nullptr, *pB = nullptr;
    cudaGetSymbolAddress(&pA, g_bufA);
    cudaGetSymbolAddress(&pB, g_bufB);
    float* bufA = (float*)pA;
    float* bufB = (float*)pB;

    k_zero <<<(NN + 255) / 256, 256>>>();
    k_count<<<(EE + 255) / 256, 256>>>(dstp);
    k_scan <<<1, 1024>>>();
    k_fill <<<(EE + 255) / 256, 256>>>(srcp, dstp);

    k_embed<<<NN / NPB, 256>>>(x, We, be, bufA);

    k_layer<<<NN / NPB, 256, LAYER_SMEM>>>(bufA, bufB,
        gW + 0 * HH * HH, gb + 0 * HH, cw + 0 * HH * HH * 3, cb + 0 * HH,
        bng + 0 * HH, bnb + 0 * HH, bnm + 0 * HH, bnv + 0 * HH);
    k_layer<<<NN / NPB, 256, LAYER_SMEM>>>(bufB, bufA,
        gW + 1 * HH * HH, gb + 1 * HH, cw + 1 * HH * HH * 3, cb + 1 * HH,
        bng + 1 * HH, bnb + 1 * HH, bnm + 1 * HH, bnv + 1 * HH);
    k_layer<<<NN / NPB, 256, LAYER_SMEM>>>(bufA, bufB,
        gW + 2 * HH * HH, gb + 2 * HH, cw + 2 * HH * HH * 3, cb + 2 * HH,
        bng + 2 * HH, bnb + 2 * HH, bnm + 2 * HH, bnv + 2 * HH);

    k_attn<<<NN / NPB, 256>>>(bufB, out,
        taw1, tab1, taw2, tab2, faw1, fab1, faw2, fab2,
        ow1, ob1, ow2, ob2);
}

// round 6
// speedup vs baseline: 1.9965x; 1.6389x over previous
#include <cuda_runtime.h>
#include <math.h>

#define NN   20000
#define EE   320000
#define TT   12
#define HH   64
#define CINN 16
#define FF   768      // TT*HH
#define NPB  8        // nodes per block

typedef unsigned long long ull;

// ---------------- scratch (static device globals) ---------------------------
__device__ float g_bufA[(size_t)NN * FF];
__device__ float g_bufB[(size_t)NN * FF];
__device__ int   g_cnt[NN];
__device__ int   g_rowptr[NN];
__device__ int   g_fill[NN];
__device__ float g_dinv[NN];
__device__ float g_selfc[NN];
__device__ int   g_col[EE];
__device__ float g_coef[EE];
// fused per-layer weights: M'[l][(c*3+k)*32+ob] pair (o=ob, o=ob+32); biases [l][3][32] pairs
__device__ float g_M[3 * 12288];
__device__ float g_B[3 * 192];

// ---------------- f32x2 helpers ---------------------------------------------
__device__ __forceinline__ ull pk2(float lo, float hi) {
    ull r; asm("mov.b64 %0,{%1,%2};" : "=l"(r) : "f"(lo), "f"(hi)); return r;
}
__device__ __forceinline__ void upk2(ull p, float& lo, float& hi) {
    asm("mov.b64 {%0,%1}, %2;" : "=f"(lo), "=f"(hi) : "l"(p));
}
__device__ __forceinline__ ull fma2(ull a, ull b, ull c) {
    ull d; asm("fma.rn.f32x2 %0,%1,%2,%3;" : "=l"(d) : "l"(a), "l"(b), "l"(c)); return d;
}

// ---------------- graph preprocessing ----------------------------------------
__global__ void k_zero() {
    int i = blockIdx.x * blockDim.x + threadIdx.x;
    if (i < NN) g_cnt[i] = 0;
}

__global__ void k_count(const int* __restrict__ dst) {
    int e = blockIdx.x * blockDim.x + threadIdx.x;
    if (e < EE) atomicAdd(&g_cnt[dst[e]], 1);
}

// single-block: exclusive scan of g_cnt -> g_rowptr, plus dinv/selfc/fill=0
__global__ void k_scan() {
    __shared__ int s[1024];
    int tid = threadIdx.x;
    int base = tid * 20;
    int loc[20], cv[20];
    int tot = 0;
#pragma unroll
    for (int i = 0; i < 20; i++) {
        int idx = base + i;
        int v = (idx < NN) ? g_cnt[idx] : 0;
        cv[i] = v; loc[i] = tot; tot += v;
    }
    s[tid] = tot;
    __syncthreads();
    for (int off = 1; off < 1024; off <<= 1) {
        int v = (tid >= off) ? s[tid - off] : 0;
        __syncthreads();
        s[tid] += v;
        __syncthreads();
    }
    int exc = s[tid] - tot;
#pragma unroll
    for (int i = 0; i < 20; i++) {
        int idx = base + i;
        if (idx < NN) {
            g_rowptr[idx] = exc + loc[i];
            g_fill[idx] = 0;
            float d = (float)(cv[i] + 1);
            g_dinv[idx]  = rsqrtf(d);
            g_selfc[idx] = 1.0f / d;
        }
    }
}

__global__ void k_fill(const int* __restrict__ src, const int* __restrict__ dst) {
    int e = blockIdx.x * blockDim.x + threadIdx.x;
    if (e < EE) {
        int s = src[e], d = dst[e];
        int p = g_rowptr[d] + atomicAdd(&g_fill[d], 1);
        g_col[p]  = s;
        g_coef[p] = g_dinv[s] * g_dinv[d];
    }
}

// ---------------- fused-weight precompute ------------------------------------
// M[o,c,k] = sum_d cw[o,d,k]*W[c,d];  M' = s_o*M  (BN scale folded)
// bias[o, t-class] = s_o*(cb[o] + sum over valid k of beta_k[o]) + h_o,
//   beta_k[o] = sum_d cw[o,d,k]*b[d]
// 16 blocks per layer; block handles 4 output channels x all 64 c.
__global__ __launch_bounds__(256) void k_prep(
    const float* __restrict__ gW, const float* __restrict__ gb,
    const float* __restrict__ cw, const float* __restrict__ cb,
    const float* __restrict__ bng, const float* __restrict__ bnb,
    const float* __restrict__ bnm, const float* __restrict__ bnv)
{
    int l  = blockIdx.x >> 4;
    int bo = blockIdx.x & 15;
    __shared__ float sWt[64 * 65];      // W transposed, padded
    __shared__ float scw4[4 * 192];     // conv weights for this block's 4 o's
    __shared__ float sb[64];
    int tid = threadIdx.x;
    const float* W   = gW + l * 4096;
    const float* cwl = cw + l * 12288;
    for (int i = tid; i < 4096; i += 256) { int c = i >> 6, d = i & 63; sWt[d * 65 + c] = W[i]; }
    for (int i = tid; i < 768; i += 256) scw4[i] = cwl[bo * 768 + i];
    if (tid < 64) sb[tid] = gb[l * 64 + tid];
    __syncthreads();

    int c = tid & 63, ol = tid >> 6;
    int o = bo * 4 + ol;
    float s = bng[l * 64 + o] * rsqrtf(bnv[l * 64 + o] + 1e-5f);
    float h = bnb[l * 64 + o] - bnm[l * 64 + o] * s;

    float m0 = 0.f, m1 = 0.f, m2 = 0.f;
#pragma unroll 4
    for (int d = 0; d < 64; d++) {
        float a = sWt[d * 65 + c];
        const float* wp = scw4 + ol * 192 + d * 3;
        m0 += a * wp[0]; m1 += a * wp[1]; m2 += a * wp[2];
    }
    float* dst = g_M + (size_t)l * 12288;
    int comp = o >> 5, ob = o & 31;
    dst[((c * 3 + 0) * 32 + ob) * 2 + comp] = s * m0;
    dst[((c * 3 + 1) * 32 + ob) * 2 + comp] = s * m1;
    dst[((c * 3 + 2) * 32 + ob) * 2 + comp] = s * m2;

    if (c == 0) {
        float b0 = 0.f, b1 = 0.f, b2 = 0.f;
#pragma unroll 4
        for (int d = 0; d < 64; d++) {
            float bd = sb[d];
            const float* wp = scw4 + ol * 192 + d * 3;
            b0 += bd * wp[0]; b1 += bd * wp[1]; b2 += bd * wp[2];
        }
        float cbo = cb[l * 64 + o];
        float Bm  = s * (cbo + b0 + b1 + b2) + h;   // t in [1,10]
        float B0v = s * (cbo + b1 + b2) + h;        // t = 0 (k=0 tap padded out)
        float B11 = s * (cbo + b0 + b1) + h;        // t = 11 (k=2 tap padded out)
        float* db = g_B + l * 192;
        db[(0 * 32 + ob) * 2 + comp] = B0v;
        db[(1 * 32 + ob) * 2 + comp] = Bm;
        db[(2 * 32 + ob) * 2 + comp] = B11;
    }
}

// ---------------- embedding --------------------------------------------------
__global__ __launch_bounds__(256) void k_embed(
    const float* __restrict__ x, const float* __restrict__ We,
    const float* __restrict__ be, float* __restrict__ out)
{
    __shared__ float sWe[CINN * HH];
    __shared__ float sbe[HH];
    __shared__ float sx[NPB][TT * CINN];
    int tid = threadIdx.x, lane = tid & 31, w = tid >> 5;
    for (int i = tid; i < CINN * HH; i += 256) sWe[i] = We[i];
    if (tid < HH) sbe[tid] = be[tid];
    int node = blockIdx.x * NPB + w;
    const float* xr = x + (size_t)node * (TT * CINN);
#pragma unroll
    for (int j = 0; j < 6; j++) sx[w][lane + 32 * j] = xr[lane + 32 * j];
    __syncthreads();
    float* orow = out + (size_t)node * FF;
#pragma unroll
    for (int t = 0; t < TT; t++) {
        float a0 = sbe[lane], a1 = sbe[lane + 32];
#pragma unroll
        for (int c = 0; c < CINN; c++) {
            float xv = sx[w][t * CINN + c];
            a0 += xv * sWe[c * HH + lane];
            a1 += xv * sWe[c * HH + lane + 32];
        }
        orow[t * HH + lane]      = fmaxf(a0, 0.f);
        orow[t * HH + lane + 32] = fmaxf(a1, 0.f);
    }
}

// ---------------- fused ST layer ---------------------------------------------
// phase1: agg = selfc*x[n] + sum_e coef*x[src]   (warp/node, float4 lanes),
//         stored DUPLICATED (v,v) pairs in smem
// phase2: out[o,t] = relu( sum_c sum_k M'[o,c,k]*agg[c,t+k-1] + bias[o,t] + x[n,o,t] )
#define LAYER_SMEM (49152 + 49152)   // sMp 48KB + dup agg 48KB

__global__ __launch_bounds__(256, 2) void k_layer(
    const float* __restrict__ xin, float* __restrict__ xout,
    const float* __restrict__ Mp, const float* __restrict__ Bp)
{
    extern __shared__ float sm[];
    ull*   sMp = (ull*)sm;               // 6144 pairs: [c*96 + k*32 + lane]
    float* sAd = sm + 12288;             // [NPB][1536] duplicated agg

    int tid = threadIdx.x, lane = tid & 31, w = tid >> 5;
    int node = blockIdx.x * NPB + w;

    // coalesced staging of fused weights (48 KB)
    const ull* gM64 = (const ull*)Mp;
    for (int i = tid; i < 6144; i += 256) sMp[i] = gM64[i];

    // ---- phase 1: CSR gather-aggregate, float4 lanes, 2x edge unroll ----
    const float4* xrow4 = (const float4*)(xin + (size_t)node * FF);
    const float4* xall4 = (const float4*)xin;
    float4 acc[6];
    float sc = g_selfc[node];
#pragma unroll
    for (int j = 0; j < 6; j++) {
        float4 v = xrow4[j * 32 + lane];
        acc[j] = make_float4(sc * v.x, sc * v.y, sc * v.z, sc * v.w);
    }
    int rp = g_rowptr[node], ne = g_cnt[node];
    int e = 0;
    for (; e + 1 < ne; e += 2) {
        int   s0 = __ldg(&g_col[rp + e]),  s1 = __ldg(&g_col[rp + e + 1]);
        float c0 = __ldg(&g_coef[rp + e]), c1 = __ldg(&g_coef[rp + e + 1]);
        const float4* r0 = xall4 + (size_t)s0 * 192;
        const float4* r1 = xall4 + (size_t)s1 * 192;
        float4 v0[6], v1[6];
#pragma unroll
        for (int j = 0; j < 6; j++) { v0[j] = r0[j * 32 + lane]; v1[j] = r1[j * 32 + lane]; }
#pragma unroll
        for (int j = 0; j < 6; j++) {
            acc[j].x += c0 * v0[j].x + c1 * v1[j].x;
            acc[j].y += c0 * v0[j].y + c1 * v1[j].y;
            acc[j].z += c0 * v0[j].z + c1 * v1[j].z;
            acc[j].w += c0 * v0[j].w + c1 * v1[j].w;
        }
    }
    if (e < ne) {
        int   s0 = __ldg(&g_col[rp + e]);
        float c0 = __ldg(&g_coef[rp + e]);
        const float4* r0 = xall4 + (size_t)s0 * 192;
#pragma unroll
        for (int j = 0; j < 6; j++) {
            float4 v = r0[j * 32 + lane];
            acc[j].x += c0 * v.x; acc[j].y += c0 * v.y;
            acc[j].z += c0 * v.z; acc[j].w += c0 * v.w;
        }
    }
    // duplicated store: dup[2f]=dup[2f+1]=flat[f], f = 128j+4lane
    float* sA = sAd + w * 1536;
#pragma unroll
    for (int j = 0; j < 6; j++) {
        float4 v = acc[j];
        int b4 = 64 * j + 2 * lane;     // float4 index
        ((float4*)sA)[b4]     = make_float4(v.x, v.x, v.y, v.y);
        ((float4*)sA)[b4 + 1] = make_float4(v.z, v.z, v.w, v.w);
    }
    __syncthreads();

    // ---- phase 2: fused GCN+conv+BN, f32x2 over (o0=lane, o1=lane+32) ----
    int d0 = lane, d1 = lane + 32;
    const ull* gB64 = (const ull*)Bp;
    ull cp[12];
    cp[0] = gB64[lane];
    ull bm = gB64[32 + lane];
#pragma unroll
    for (int t = 1; t < 11; t++) cp[t] = bm;
    cp[11] = gB64[64 + lane];

    const ull* sA2 = (const ull*)sA;
#pragma unroll 2
    for (int c = 0; c < 64; c++) {
        const ull* Mw = sMp + c * 96;
        ull M0 = Mw[lane], M1 = Mw[32 + lane], M2 = Mw[64 + lane];
        const ull* ad = sA2 + c * 12;
#pragma unroll
        for (int t = 0; t < 12; t++) {
            ull a = ad[t];                       // LDS.64 broadcast, (v,v)
            if (t < 11) cp[t + 1] = fma2(a, M0, cp[t + 1]);
            cp[t] = fma2(a, M1, cp[t]);
            if (t > 0)  cp[t - 1] = fma2(a, M2, cp[t - 1]);
        }
    }

    // ---- epilogue: residual + relu + store ----
    float4* orow4 = (float4*)(xout + (size_t)node * FF);
#pragma unroll
    for (int q = 0; q < 3; q++) {
        float4 r0 = xrow4[d0 * 3 + q];
        float4 r1 = xrow4[d1 * 3 + q];
        float c0a, c1a, c0b, c1b, c0c, c1c, c0d, c1d;
        upk2(cp[q * 4 + 0], c0a, c1a);
        upk2(cp[q * 4 + 1], c0b, c1b);
        upk2(cp[q * 4 + 2], c0c, c1c);
        upk2(cp[q * 4 + 3], c0d, c1d);
        orow4[d0 * 3 + q] = make_float4(
            fmaxf(c0a + r0.x, 0.f), fmaxf(c0b + r0.y, 0.f),
            fmaxf(c0c + r0.z, 0.f), fmaxf(c0d + r0.w, 0.f));
        orow4[d1 * 3 + q] = make_float4(
            fmaxf(c1a + r1.x, 0.f), fmaxf(c1b + r1.y, 0.f),
            fmaxf(c1c + r1.z, 0.f), fmaxf(c1d + r1.w, 0.f));
    }
}

// ---------------- dual attention pooling + output MLP ------------------------
__global__ __launch_bounds__(256) void k_attn(
    const float* __restrict__ xin, float* __restrict__ out,
    const float* __restrict__ taw1, const float* __restrict__ tab1,
    const float* __restrict__ taw2, const float* __restrict__ tab2,
    const float* __restrict__ faw1, const float* __restrict__ fab1,
    const float* __restrict__ faw2, const float* __restrict__ fab2,
    const float* __restrict__ ow1,  const float* __restrict__ ob1,
    const float* __restrict__ ow2,  const float* __restrict__ ob2)
{
    __shared__ float sXa[NPB][FF];
    __shared__ float sTW1[HH * 32];
    __shared__ float sOW1[HH * 32];
    __shared__ float sTB1[32], sTW2[32], sOB1[32], sOW2[32];
    __shared__ float sFW1[TT * 6], sFB1[6], sFW2[6];

    int tid = threadIdx.x, lane = tid & 31, w = tid >> 5;
    for (int i = tid; i < HH * 32; i += 256) { sTW1[i] = taw1[i]; sOW1[i] = ow1[i]; }
    if (tid < 32) { sTB1[tid] = tab1[tid]; sTW2[tid] = taw2[tid];
                    sOB1[tid] = ob1[tid];  sOW2[tid] = ow2[tid]; }
    if (tid < TT * 6) sFW1[tid] = faw1[tid];
    if (tid < 6) { sFB1[tid] = fab1[tid]; sFW2[tid] = faw2[tid]; }

    int node = blockIdx.x * NPB + w;
    const float4* xr4 = (const float4*)(xin + (size_t)node * FF);
#pragma unroll
    for (int j = 0; j < 6; j++) ((float4*)sXa[w])[j * 32 + lane] = xr4[j * 32 + lane];
    __syncthreads();

    float tab2v = tab2[0], fab2v = fab2[0], ob2v = ob2[0];

    float tw[12];
#pragma unroll
    for (int t = 0; t < 12; t++) {
        float m = sTB1[lane];
#pragma unroll
        for (int h = 0; h < 64; h++) m += sXa[w][t * 64 + h] * sTW1[h * 32 + lane];
        m = fmaxf(m, 0.f);
        float c = m * sTW2[lane];
#pragma unroll
        for (int off = 16; off; off >>= 1) c += __shfl_xor_sync(0xffffffffu, c, off);
        tw[t] = c + tab2v;
    }
    float mx = tw[0];
#pragma unroll
    for (int t = 1; t < 12; t++) mx = fmaxf(mx, tw[t]);
    float ssum = 0.f;
#pragma unroll
    for (int t = 0; t < 12; t++) { tw[t] = expf(tw[t] - mx); ssum += tw[t]; }
    float inv = 1.f / ssum;
#pragma unroll
    for (int t = 0; t < 12; t++) tw[t] *= inv;

    float xt0[12], xt1[12];
#pragma unroll
    for (int t = 0; t < 12; t++) {
        xt0[t] = sXa[w][t * 64 + lane]      * tw[t];
        xt1[t] = sXa[w][t * 64 + lane + 32] * tw[t];
    }
    float fs0 = fab2v, fs1 = fab2v;
#pragma unroll
    for (int j = 0; j < 6; j++) {
        float v0 = sFB1[j], v1 = sFB1[j];
#pragma unroll
        for (int t = 0; t < 12; t++) {
            float wv = sFW1[t * 6 + j];
            v0 += xt0[t] * wv;
            v1 += xt1[t] * wv;
        }
        v0 = fmaxf(v0, 0.f); v1 = fmaxf(v1, 0.f);
        float w2 = sFW2[j];
        fs0 += v0 * w2; fs1 += v1 * w2;
    }
    float m2 = fmaxf(fs0, fs1);
#pragma unroll
    for (int off = 16; off; off >>= 1) m2 = fmaxf(m2, __shfl_xor_sync(0xffffffffu, m2, off));
    float e0 = expf(fs0 - m2), e1 = expf(fs1 - m2);
    float es = e0 + e1;
#pragma unroll
    for (int off = 16; off; off >>= 1) es += __shfl_xor_sync(0xffffffffu, es, off);
    float fw0 = e0 / es, fw1 = e1 / es;

    float sum0 = 0.f, sum1 = 0.f;
#pragma unroll
    for (int t = 0; t < 12; t++) { sum0 += xt0[t]; sum1 += xt1[t]; }
    float xf0 = fw0 * sum0, xf1 = fw1 * sum1;

    __syncwarp();
    sXa[w][lane] = xf0; sXa[w][lane + 32] = xf1;
    __syncwarp();

    float y = sOB1[lane];
#pragma unroll
    for (int h = 0; h < 64; h++) y += sXa[w][h] * sOW1[h * 32 + lane];
    y = fmaxf(y, 0.f);
    float c2 = y * sOW2[lane];
#pragma unroll
    for (int off = 16; off; off >>= 1) c2 += __shfl_xor_sync(0xffffffffu, c2, off);
    if (lane == 0) out[node] = c2 + ob2v;
}

// ---------------- launch ------------------------------------------------------
extern "C" void kernel_launch(void* const* d_in, const int* in_sizes, int n_in,
                              void* d_out, int out_size)
{
    const float* x    = (const float*)d_in[0];
    const int*   ei   = (const int*)d_in[1];
    const int*   srcp = ei;
    const int*   dstp = ei + EE;
    const float* We   = (const float*)d_in[2];
    const float* be   = (const float*)d_in[3];
    const float* gW   = (const float*)d_in[4];
    const float* gb   = (const float*)d_in[5];
    const float* cw   = (const float*)d_in[6];
    const float* cb   = (const float*)d_in[7];
    const float* bng  = (const float*)d_in[8];
    const float* bnb  = (const float*)d_in[9];
    const float* bnm  = (const float*)d_in[10];
    const float* bnv  = (const float*)d_in[11];
    const float* taw1 = (const float*)d_in[12];
    const float* tab1 = (const float*)d_in[13];
    const float* taw2 = (const float*)d_in[14];
    const float* tab2 = (const float*)d_in[15];
    const float* faw1 = (const float*)d_in[16];
    const float* fab1 = (const float*)d_in[17];
    const float* faw2 = (const float*)d_in[18];
    const float* fab2 = (const float*)d_in[19];
    const float* ow1  = (const float*)d_in[20];
    const float* ob1  = (const float*)d_in[21];
    const float* ow2  = (const float*)d_in[22];
    const float* ob2  = (const float*)d_in[23];
    float* out = (float*)d_out;

    cudaFuncSetAttribute(k_layer, cudaFuncAttributeMaxDynamicSharedMemorySize, LAYER_SMEM);

    void *pA = nullptr, *pB = nullptr, *pM = nullptr, *pBi = nullptr;
    cudaGetSymbolAddress(&pA, g_bufA);
    cudaGetSymbolAddress(&pB, g_bufB);
    cudaGetSymbolAddress(&pM, g_M);
    cudaGetSymbolAddress(&pBi, g_B);
    float* bufA = (float*)pA;
    float* bufB = (float*)pB;
    const float* Mb = (const float*)pM;
    const float* Bb = (const float*)pBi;

    k_zero <<<(NN + 255) / 256, 256>>>();
    k_count<<<(EE + 255) / 256, 256>>>(dstp);
    k_scan <<<1, 1024>>>();
    k_fill <<<(EE + 255) / 256, 256>>>(srcp, dstp);
    k_prep <<<48, 256>>>(gW, gb, cw, cb, bng, bnb, bnm, bnv);

    k_embed<<<NN / NPB, 256>>>(x, We, be, bufA);

    k_layer<<<NN / NPB, 256, LAYER_SMEM>>>(bufA, bufB, Mb + 0 * 12288, Bb + 0 * 192);
    k_layer<<<NN / NPB, 256, LAYER_SMEM>>>(bufB, bufA, Mb + 1 * 12288, Bb + 1 * 192);
    k_layer<<<NN / NPB, 256, LAYER_SMEM>>>(bufA, bufB, Mb + 2 * 12288, Bb + 2 * 192);

    k_attn<<<NN / NPB, 256>>>(bufB, out,
        taw1, tab1, taw2, tab2, faw1, fab1, faw2, fab2,
        ow1, ob1, ow2, ob2);
}

// round 7
// speedup vs baseline: 1.9997x; 1.0016x over previous
#include <cuda_runtime.h>
#include <math.h>

#define NN   20000
#define EE   320000
#define TT   12
#define HH   64
#define CINN 16
#define FF   768      // TT*HH
#define NPB  8        // warps per block

typedef unsigned long long ull;

// ---------------- scratch (static device globals) ---------------------------
__device__ float g_bufA[(size_t)NN * FF];
__device__ float g_bufB[(size_t)NN * FF];
__device__ int   g_cnt[NN];
__device__ int   g_rowptr[NN];
__device__ int   g_fill[NN];
__device__ float g_dinv[NN];
__device__ float g_selfc[NN];
__device__ int   g_col[EE];
__device__ float g_coef[EE];
// fused per-layer weights (12288 floats per layer):
//   region1 (8192 floats): float idx (c*32+ob)*4 + k*2 + comp   for k in {0,1}
//   region2 (4096 floats): 8192 + (c*32+ob)*2 + comp            for k = 2
__device__ float g_M[3 * 12288];
__device__ float g_B[3 * 192];

// ---------------- f32x2 helpers ---------------------------------------------
__device__ __forceinline__ ull pk2(float lo, float hi) {
    ull r; asm("mov.b64 %0,{%1,%2};" : "=l"(r) : "f"(lo), "f"(hi)); return r;
}
__device__ __forceinline__ void upk2(ull p, float& lo, float& hi) {
    asm("mov.b64 {%0,%1}, %2;" : "=f"(lo), "=f"(hi) : "l"(p));
}
__device__ __forceinline__ ull fma2(ull a, ull b, ull c) {
    ull d; asm("fma.rn.f32x2 %0,%1,%2,%3;" : "=l"(d) : "l"(a), "l"(b), "l"(c)); return d;
}

// ---------------- graph preprocessing ----------------------------------------
__global__ void k_zero() {
    int i = blockIdx.x * blockDim.x + threadIdx.x;
    if (i < NN) g_cnt[i] = 0;
}

__global__ void k_count(const int* __restrict__ dst) {
    int e = blockIdx.x * blockDim.x + threadIdx.x;
    if (e < EE) atomicAdd(&g_cnt[dst[e]], 1);
}

// single-block: exclusive scan of g_cnt -> g_rowptr, plus dinv/selfc/fill=0
__global__ void k_scan() {
    __shared__ int s[1024];
    int tid = threadIdx.x;
    int base = tid * 20;
    int loc[20], cv[20];
    int tot = 0;
#pragma unroll
    for (int i = 0; i < 20; i++) {
        int idx = base + i;
        int v = (idx < NN) ? g_cnt[idx] : 0;
        cv[i] = v; loc[i] = tot; tot += v;
    }
    s[tid] = tot;
    __syncthreads();
    for (int off = 1; off < 1024; off <<= 1) {
        int v = (tid >= off) ? s[tid - off] : 0;
        __syncthreads();
        s[tid] += v;
        __syncthreads();
    }
    int exc = s[tid] - tot;
#pragma unroll
    for (int i = 0; i < 20; i++) {
        int idx = base + i;
        if (idx < NN) {
            g_rowptr[idx] = exc + loc[i];
            g_fill[idx] = 0;
            float d = (float)(cv[i] + 1);
            g_dinv[idx]  = rsqrtf(d);
            g_selfc[idx] = 1.0f / d;
        }
    }
}

__global__ void k_fill(const int* __restrict__ src, const int* __restrict__ dst) {
    int e = blockIdx.x * blockDim.x + threadIdx.x;
    if (e < EE) {
        int s = src[e], d = dst[e];
        int p = g_rowptr[d] + atomicAdd(&g_fill[d], 1);
        g_col[p]  = s;
        g_coef[p] = g_dinv[s] * g_dinv[d];
    }
}

// ---------------- fused-weight precompute ------------------------------------
// M[o,c,k] = sum_d cw[o,d,k]*W[c,d];  M' = s_o*M  (BN scale folded)
__global__ __launch_bounds__(256) void k_prep(
    const float* __restrict__ gW, const float* __restrict__ gb,
    const float* __restrict__ cw, const float* __restrict__ cb,
    const float* __restrict__ bng, const float* __restrict__ bnb,
    const float* __restrict__ bnm, const float* __restrict__ bnv)
{
    int l  = blockIdx.x >> 4;
    int bo = blockIdx.x & 15;
    __shared__ float sWt[64 * 65];
    __shared__ float scw4[4 * 192];
    __shared__ float sb[64];
    int tid = threadIdx.x;
    const float* W   = gW + l * 4096;
    const float* cwl = cw + l * 12288;
    for (int i = tid; i < 4096; i += 256) { int c = i >> 6, d = i & 63; sWt[d * 65 + c] = W[i]; }
    for (int i = tid; i < 768; i += 256) scw4[i] = cwl[bo * 768 + i];
    if (tid < 64) sb[tid] = gb[l * 64 + tid];
    __syncthreads();

    int c = tid & 63, ol = tid >> 6;
    int o = bo * 4 + ol;
    float s = bng[l * 64 + o] * rsqrtf(bnv[l * 64 + o] + 1e-5f);
    float h = bnb[l * 64 + o] - bnm[l * 64 + o] * s;

    float m0 = 0.f, m1 = 0.f, m2 = 0.f;
#pragma unroll 4
    for (int d = 0; d < 64; d++) {
        float a = sWt[d * 65 + c];
        const float* wp = scw4 + ol * 192 + d * 3;
        m0 += a * wp[0]; m1 += a * wp[1]; m2 += a * wp[2];
    }
    float* dst = g_M + (size_t)l * 12288;
    int comp = o >> 5, ob = o & 31;
    dst[(c * 32 + ob) * 4 + 0 + comp]        = s * m0;   // k=0 pair
    dst[(c * 32 + ob) * 4 + 2 + comp]        = s * m1;   // k=1 pair
    dst[8192 + (c * 32 + ob) * 2 + comp]     = s * m2;   // k=2 pair

    if (c == 0) {
        float b0 = 0.f, b1 = 0.f, b2 = 0.f;
#pragma unroll 4
        for (int d = 0; d < 64; d++) {
            float bd = sb[d];
            const float* wp = scw4 + ol * 192 + d * 3;
            b0 += bd * wp[0]; b1 += bd * wp[1]; b2 += bd * wp[2];
        }
        float cbo = cb[l * 64 + o];
        float Bm  = s * (cbo + b0 + b1 + b2) + h;   // t in [1,10]
        float B0v = s * (cbo + b1 + b2) + h;        // t = 0
        float B11 = s * (cbo + b0 + b1) + h;        // t = 11
        float* db = g_B + l * 192;
        db[(0 * 32 + ob) * 2 + comp] = B0v;
        db[(1 * 32 + ob) * 2 + comp] = Bm;
        db[(2 * 32 + ob) * 2 + comp] = B11;
    }
}

// ---------------- embedding --------------------------------------------------
__global__ __launch_bounds__(256) void k_embed(
    const float* __restrict__ x, const float* __restrict__ We,
    const float* __restrict__ be, float* __restrict__ out)
{
    __shared__ float sWe[CINN * HH];
    __shared__ float sbe[HH];
    __shared__ float sx[NPB][TT * CINN];
    int tid = threadIdx.x, lane = tid & 31, w = tid >> 5;
    for (int i = tid; i < CINN * HH; i += 256) sWe[i] = We[i];
    if (tid < HH) sbe[tid] = be[tid];
    int node = blockIdx.x * NPB + w;
    const float* xr = x + (size_t)node * (TT * CINN);
#pragma unroll
    for (int j = 0; j < 6; j++) sx[w][lane + 32 * j] = xr[lane + 32 * j];
    __syncthreads();
    float* orow = out + (size_t)node * FF;
#pragma unroll
    for (int t = 0; t < TT; t++) {
        float a0 = sbe[lane], a1 = sbe[lane + 32];
#pragma unroll
        for (int c = 0; c < CINN; c++) {
            float xv = sx[w][t * CINN + c];
            a0 += xv * sWe[c * HH + lane];
            a1 += xv * sWe[c * HH + lane + 32];
        }
        orow[t * HH + lane]      = fmaxf(a0, 0.f);
        orow[t * HH + lane + 32] = fmaxf(a1, 0.f);
    }
}

// ---------------- fused ST layer ---------------------------------------------
// warp processes NODES_PER_WARP nodes sequentially; NO inter-warp syncs after
// weight staging, so warps drift and the SM overlaps L2-bound gathers with
// FMA-bound transforms.
#define NODES_PER_WARP 2
#define LAYER_SMEM (49152 + 49152)   // weights 48KB + dup agg 48KB

__global__ __launch_bounds__(256, 2) void k_layer(
    const float* __restrict__ xin, float* __restrict__ xout,
    const float* __restrict__ Mp, const float* __restrict__ Bp)
{
    extern __shared__ float sm[];
    ulonglong2* sM01 = (ulonglong2*)sm;            // [c*32+lane] (M0pair,M1pair) 32KB
    ull*        sM2v = ((ull*)sm) + 4096;          // [c*32+lane] M2pair          16KB
    float*      sAd  = sm + 12288;                 // per-warp 1536 floats dup agg

    int tid = threadIdx.x, lane = tid & 31, w = tid >> 5;

    // coalesced staging of fused weights (48 KB)
    {
        const ull* gM64 = (const ull*)Mp;
        ull* sW64 = (ull*)sm;
        for (int i = tid; i < 6144; i += 256) sW64[i] = gM64[i];
    }
    __syncthreads();   // the ONLY block-wide sync

    // bias pairs (loop-invariant)
    const ull* gB64 = (const ull*)Bp;
    ull b0v = gB64[lane], bmv = gB64[32 + lane], b11v = gB64[64 + lane];

    float* sA = sAd + w * 1536;
    const float4* xall4 = (const float4*)xin;

#pragma unroll 1
    for (int it = 0; it < NODES_PER_WARP; it++) {
        int node = (blockIdx.x * NPB + w) * NODES_PER_WARP + it;

        // ---- phase 1: CSR gather-aggregate, float4 lanes, 2x edge unroll ----
        const float4* xrow4 = xall4 + (size_t)node * 192;
        float4 acc[6];
        float sc = g_selfc[node];
#pragma unroll
        for (int j = 0; j < 6; j++) {
            float4 v = xrow4[j * 32 + lane];
            acc[j] = make_float4(sc * v.x, sc * v.y, sc * v.z, sc * v.w);
        }
        int rp = g_rowptr[node], ne = g_cnt[node];
        int e = 0;
        for (; e + 1 < ne; e += 2) {
            int   s0 = __ldg(&g_col[rp + e]),  s1 = __ldg(&g_col[rp + e + 1]);
            float c0 = __ldg(&g_coef[rp + e]), c1 = __ldg(&g_coef[rp + e + 1]);
            const float4* r0 = xall4 + (size_t)s0 * 192;
            const float4* r1 = xall4 + (size_t)s1 * 192;
            float4 v0[6], v1[6];
#pragma unroll
            for (int j = 0; j < 6; j++) { v0[j] = r0[j * 32 + lane]; v1[j] = r1[j * 32 + lane]; }
#pragma unroll
            for (int j = 0; j < 6; j++) {
                acc[j].x += c0 * v0[j].x + c1 * v1[j].x;
                acc[j].y += c0 * v0[j].y + c1 * v1[j].y;
                acc[j].z += c0 * v0[j].z + c1 * v1[j].z;
                acc[j].w += c0 * v0[j].w + c1 * v1[j].w;
            }
        }
        if (e < ne) {
            int   s0 = __ldg(&g_col[rp + e]);
            float c0 = __ldg(&g_coef[rp + e]);
            const float4* r0 = xall4 + (size_t)s0 * 192;
#pragma unroll
            for (int j = 0; j < 6; j++) {
                float4 v = r0[j * 32 + lane];
                acc[j].x += c0 * v.x; acc[j].y += c0 * v.y;
                acc[j].z += c0 * v.z; acc[j].w += c0 * v.w;
            }
        }
        __syncwarp();   // prev iteration's readers done before overwrite
        // duplicated store: dup[2f]=dup[2f+1]=flat[f], f = 128j+4lane
#pragma unroll
        for (int j = 0; j < 6; j++) {
            float4 v = acc[j];
            int b4 = 64 * j + 2 * lane;
            ((float4*)sA)[b4]     = make_float4(v.x, v.x, v.y, v.y);
            ((float4*)sA)[b4 + 1] = make_float4(v.z, v.z, v.w, v.w);
        }
        __syncwarp();   // make dup agg visible within warp

        // ---- phase 2: fused GCN+conv+BN, f32x2 over (o0=lane, o1=lane+32) ----
        ull cp[12];
        cp[0] = b0v;
#pragma unroll
        for (int t = 1; t < 11; t++) cp[t] = bmv;
        cp[11] = b11v;

        const ull* sA2 = (const ull*)sA;
#pragma unroll 2
        for (int c = 0; c < 64; c++) {
            ulonglong2 m01 = sM01[c * 32 + lane];
            ull M2 = sM2v[c * 32 + lane];
            const ulonglong2* ad2 = (const ulonglong2*)(sA2 + c * 12);
#pragma unroll
            for (int j = 0; j < 6; j++) {
                ulonglong2 av = ad2[j];     // (a[2j],a[2j]) , (a[2j+1],a[2j+1])
                int t0 = 2 * j, t1 = t0 + 1;
                cp[t0 + 1] = fma2(av.x, m01.x, cp[t0 + 1]);
                cp[t0]     = fma2(av.x, m01.y, cp[t0]);
                if (t0 > 0)  cp[t0 - 1] = fma2(av.x, M2, cp[t0 - 1]);
                if (t1 < 11) cp[t1 + 1] = fma2(av.y, m01.x, cp[t1 + 1]);
                cp[t1]     = fma2(av.y, m01.y, cp[t1]);
                cp[t1 - 1] = fma2(av.y, M2, cp[t1 - 1]);
            }
        }

        // ---- epilogue: residual + relu + store ----
        int d0 = lane, d1 = lane + 32;
        float4* orow4 = (float4*)(xout + (size_t)node * FF);
#pragma unroll
        for (int q = 0; q < 3; q++) {
            float4 r0 = xrow4[d0 * 3 + q];
            float4 r1 = xrow4[d1 * 3 + q];
            float c0a, c1a, c0b, c1b, c0c, c1c, c0d, c1d;
            upk2(cp[q * 4 + 0], c0a, c1a);
            upk2(cp[q * 4 + 1], c0b, c1b);
            upk2(cp[q * 4 + 2], c0c, c1c);
            upk2(cp[q * 4 + 3], c0d, c1d);
            orow4[d0 * 3 + q] = make_float4(
                fmaxf(c0a + r0.x, 0.f), fmaxf(c0b + r0.y, 0.f),
                fmaxf(c0c + r0.z, 0.f), fmaxf(c0d + r0.w, 0.f));
            orow4[d1 * 3 + q] = make_float4(
                fmaxf(c1a + r1.x, 0.f), fmaxf(c1b + r1.y, 0.f),
                fmaxf(c1c + r1.z, 0.f), fmaxf(c1d + r1.w, 0.f));
        }
    }
}

// ---------------- dual attention pooling + output MLP ------------------------
__global__ __launch_bounds__(256) void k_attn(
    const float* __restrict__ xin, float* __restrict__ out,
    const float* __restrict__ taw1, const float* __restrict__ tab1,
    const float* __restrict__ taw2, const float* __restrict__ tab2,
    const float* __restrict__ faw1, const float* __restrict__ fab1,
    const float* __restrict__ faw2, const float* __restrict__ fab2,
    const float* __restrict__ ow1,  const float* __restrict__ ob1,
    const float* __restrict__ ow2,  const float* __restrict__ ob2)
{
    __shared__ float sXa[NPB][FF];
    __shared__ float sTW1[HH * 32];
    __shared__ float sOW1[HH * 32];
    __shared__ float sTB1[32], sTW2[32], sOB1[32], sOW2[32];
    __shared__ float sFW1[TT * 6], sFB1[6], sFW2[6];

    int tid = threadIdx.x, lane = tid & 31, w = tid >> 5;
    for (int i = tid; i < HH * 32; i += 256) { sTW1[i] = taw1[i]; sOW1[i] = ow1[i]; }
    if (tid < 32) { sTB1[tid] = tab1[tid]; sTW2[tid] = taw2[tid];
                    sOB1[tid] = ob1[tid];  sOW2[tid] = ow2[tid]; }
    if (tid < TT * 6) sFW1[tid] = faw1[tid];
    if (tid < 6) { sFB1[tid] = fab1[tid]; sFW2[tid] = faw2[tid]; }

    int node = blockIdx.x * NPB + w;
    const float4* xr4 = (const float4*)(xin + (size_t)node * FF);
#pragma unroll
    for (int j = 0; j < 6; j++) ((float4*)sXa[w])[j * 32 + lane] = xr4[j * 32 + lane];
    __syncthreads();

    float tab2v = tab2[0], fab2v = fab2[0], ob2v = ob2[0];

    float tw[12];
#pragma unroll
    for (int t = 0; t < 12; t++) {
        float m = sTB1[lane];
#pragma unroll
        for (int h = 0; h < 64; h++) m += sXa[w][t * 64 + h] * sTW1[h * 32 + lane];
        m = fmaxf(m, 0.f);
        float c = m * sTW2[lane];
#pragma unroll
        for (int off = 16; off; off >>= 1) c += __shfl_xor_sync(0xffffffffu, c, off);
        tw[t] = c + tab2v;
    }
    float mx = tw[0];
#pragma unroll
    for (int t = 1; t < 12; t++) mx = fmaxf(mx, tw[t]);
    float ssum = 0.f;
#pragma unroll
    for (int t = 0; t < 12; t++) { tw[t] = expf(tw[t] - mx); ssum += tw[t]; }
    float inv = 1.f / ssum;
#pragma unroll
    for (int t = 0; t < 12; t++) tw[t] *= inv;

    float xt0[12], xt1[12];
#pragma unroll
    for (int t = 0; t < 12; t++) {
        xt0[t] = sXa[w][t * 64 + lane]      * tw[t];
        xt1[t] = sXa[w][t * 64 + lane + 32] * tw[t];
    }
    float fs0 = fab2v, fs1 = fab2v;
#pragma unroll
    for (int j = 0; j < 6; j++) {
        float v0 = sFB1[j], v1 = sFB1[j];
#pragma unroll
        for (int t = 0; t < 12; t++) {
            float wv = sFW1[t * 6 + j];
            v0 += xt0[t] * wv;
            v1 += xt1[t] * wv;
        }
        v0 = fmaxf(v0, 0.f); v1 = fmaxf(v1, 0.f);
        float w2 = sFW2[j];
        fs0 += v0 * w2; fs1 += v1 * w2;
    }
    float m2 = fmaxf(fs0, fs1);
#pragma unroll
    for (int off = 16; off; off >>= 1) m2 = fmaxf(m2, __shfl_xor_sync(0xffffffffu, m2, off));
    float e0 = expf(fs0 - m2), e1 = expf(fs1 - m2);
    float es = e0 + e1;
#pragma unroll
    for (int off = 16; off; off >>= 1) es += __shfl_xor_sync(0xffffffffu, es, off);
    float fw0 = e0 / es, fw1 = e1 / es;

    float sum0 = 0.f, sum1 = 0.f;
#pragma unroll
    for (int t = 0; t < 12; t++) { sum0 += xt0[t]; sum1 += xt1[t]; }
    float xf0 = fw0 * sum0, xf1 = fw1 * sum1;

    __syncwarp();
    sXa[w][lane] = xf0; sXa[w][lane + 32] = xf1;
    __syncwarp();

    float y = sOB1[lane];
#pragma unroll
    for (int h = 0; h < 64; h++) y += sXa[w][h] * sOW1[h * 32 + lane];
    y = fmaxf(y, 0.f);
    float c2 = y * sOW2[lane];
#pragma unroll
    for (int off = 16; off; off >>= 1) c2 += __shfl_xor_sync(0xffffffffu, c2, off);
    if (lane == 0) out[node] = c2 + ob2v;
}

// ---------------- launch ------------------------------------------------------
extern "C" void kernel_launch(void* const* d_in, const int* in_sizes, int n_in,
                              void* d_out, int out_size)
{
    const float* x    = (const float*)d_in[0];
    const int*   ei   = (const int*)d_in[1];
    const int*   srcp = ei;
    const int*   dstp = ei + EE;
    const float* We   = (const float*)d_in[2];
    const float* be   = (const float*)d_in[3];
    const float* gW   = (const float*)d_in[4];
    const float* gb   = (const float*)d_in[5];
    const float* cw   = (const float*)d_in[6];
    const float* cb   = (const float*)d_in[7];
    const float* bng  = (const float*)d_in[8];
    const float* bnb  = (const float*)d_in[9];
    const float* bnm  = (const float*)d_in[10];
    const float* bnv  = (const float*)d_in[11];
    const float* taw1 = (const float*)d_in[12];
    const float* tab1 = (const float*)d_in[13];
    const float* taw2 = (const float*)d_in[14];
    const float* tab2 = (const float*)d_in[15];
    const float* faw1 = (const float*)d_in[16];
    const float* fab1 = (const float*)d_in[17];
    const float* faw2 = (const float*)d_in[18];
    const float* fab2 = (const float*)d_in[19];
    const float* ow1  = (const float*)d_in[20];
    const float* ob1  = (const float*)d_in[21];
    const float* ow2  = (const float*)d_in[22];
    const float* ob2  = (const float*)d_in[23];
    float* out = (float*)d_out;

    cudaFuncSetAttribute(k_layer, cudaFuncAttributeMaxDynamicSharedMemorySize, LAYER_SMEM);

    void *pA = nullptr, *pB = nullptr, *pM = nullptr, *pBi = nullptr;
    cudaGetSymbolAddress(&pA, g_bufA);
    cudaGetSymbolAddress(&pB, g_bufB);
    cudaGetSymbolAddress(&pM, g_M);
    cudaGetSymbolAddress(&pBi, g_B);
    float* bufA = (float*)pA;
    float* bufB = (float*)pB;
    const float* Mb = (const float*)pM;
    const float* Bb = (const float*)pBi;

    k_zero <<<(NN + 255) / 256, 256>>>();
    k_count<<<(EE + 255) / 256, 256>>>(dstp);
    k_scan <<<1, 1024>>>();
    k_fill <<<(EE + 255) / 256, 256>>>(srcp, dstp);
    k_prep <<<48, 256>>>(gW, gb, cw, cb, bng, bnb, bnm, bnv);

    k_embed<<<NN / NPB, 256>>>(x, We, be, bufA);

    int lgrid = NN / (NPB * NODES_PER_WARP);   // 1250
    k_layer<<<lgrid, 256, LAYER_SMEM>>>(bufA, bufB, Mb + 0 * 12288, Bb + 0 * 192);
    k_layer<<<lgrid, 256, LAYER_SMEM>>>(bufB, bufA, Mb + 1 * 12288, Bb + 1 * 192);
    k_layer<<<lgrid, 256, LAYER_SMEM>>>(bufA, bufB, Mb + 2 * 12288, Bb + 2 * 192);

    k_attn<<<NN / NPB, 256>>>(bufB, out,
        taw1, tab1, taw2, tab2, faw1, fab1, faw2, fab2,
        ow1, ob1, ow2, ob2);
}